// round 1
// baseline (speedup 1.0000x reference)
#include <cuda_runtime.h>

#define N_NODES 50000
#define N_EDGES 800000
#define NODE_F  160     // 64 scalar + 32*3 vector
#define S_F     384     // s0:64  s1:192  s2:96  s3:32
#define TE      16      // edges per block in edge kernel

// Scratch (device globals — no allocations allowed)
__device__ float g_l[N_NODES * NODE_F];   // l0 (64) then l1 (u*3+d), per node
__device__ float g_s[N_NODES * S_F];      // scatter accumulators

// ---------------------------------------------------------------------------
__global__ void zero_s_kernel() {
    const int n4 = N_NODES * S_F / 4;
    float4* p = reinterpret_cast<float4*>(g_s);
    float4 z = make_float4(0.f, 0.f, 0.f, 0.f);
    for (int i = blockIdx.x * blockDim.x + threadIdx.x; i < n4;
         i += gridDim.x * blockDim.x)
        p[i] = z;
}

// ---------------------------------------------------------------------------
// Node pre-pass: si -> out, l -> g_l. One block (160 thr) per node.
__global__ void node_pre_kernel(const float* __restrict__ x,
                                const float* __restrict__ attr,
                                const float* __restrict__ Wsi0,
                                const float* __restrict__ Wsi1,
                                const float* __restrict__ Wl10,
                                const float* __restrict__ Wl11,
                                float* __restrict__ out) {
    __shared__ float xs[NODE_F];
    const int n = blockIdx.x;
    const int t = threadIdx.x;
    xs[t] = x[n * NODE_F + t];
    __syncthreads();
    const float a = attr[n];
    if (t < 64) {
        float accS = 0.f, accL = 0.f;
#pragma unroll
        for (int u = 0; u < 64; u++) {
            const float xv = xs[u];
            accS += xv * Wsi0[u * 64 + t];
            accL += xv * Wl10[u * 64 + t];
        }
        const float s = a * 0.125f;                      // 1/sqrt(64)
        out[n * NODE_F + t] = accS * s;
        g_l[n * NODE_F + t] = accL * s;
    } else {
        const int idx = t - 64;
        const int w = idx / 3, d = idx - w * 3;
        float accS = 0.f, accL = 0.f;
#pragma unroll
        for (int u = 0; u < 32; u++) {
            const float xv = xs[64 + u * 3 + d];
            accS += xv * Wsi1[u * 32 + w];
            accL += xv * Wl11[u * 32 + w];
        }
        const float s = a * 0.1767766952966369f;         // 1/sqrt(32)
        out[n * NODE_F + t] = accS * s;
        g_l[n * NODE_F + t] = accL * s;
    }
}

// ---------------------------------------------------------------------------
// Edge pass: radial MLP + tensor-product messages + atomic scatter.
// 192 threads, TE=16 edges per block. Thread t owns output feature t.
__global__ void __launch_bounds__(192)
edge_kernel(const float* __restrict__ elemb,
            const float* __restrict__ eattr,
            const int*   __restrict__ esrc,
            const int*   __restrict__ edst,
            const float* __restrict__ Wfc1,
            const float* __restrict__ Wfc2) {
    __shared__ __align__(16) float sh_h[100][TE];
    __shared__ float sh_el[TE][10];
    __shared__ float sh_ea[TE][4];
    __shared__ int   sh_src[TE];
    __shared__ int   sh_dst[TE];

    const int t  = threadIdx.x;
    const int e0 = blockIdx.x * TE;

    for (int i = t; i < TE * 10; i += 192)
        sh_el[i / 10][i % 10] = elemb[e0 * 10 + i];
    if (t < TE * 4)
        sh_ea[t >> 2][t & 3] = eattr[e0 * 4 + t];
    if (t >= 64 && t < 64 + TE) {
        sh_src[t - 64] = esrc[e0 + t - 64];
        sh_dst[t - 64] = edst[e0 + t - 64];
    }
    __syncthreads();

    // Phase A: H = relu(elemb @ Wfc1 / sqrt(10)) * sqrt(2), stored [k][e]
    for (int idx = t; idx < 100 * TE; idx += 192) {
        const int e = idx % TE, k = idx / TE;
        float acc = 0.f;
#pragma unroll
        for (int b = 0; b < 10; b++)
            acc += sh_el[e][b] * Wfc1[b * 100 + k];
        acc *= 0.31622776601683794f;                     // 1/sqrt(10)
        sh_h[k][e] = fmaxf(acc, 0.f) * 1.4142135623730951f;  // relu gain
    }
    __syncthreads();

    // Phase B: w[t] per edge = sum_k H[e][k] * Wfc2[k][t]
    float acc[TE];
#pragma unroll
    for (int e = 0; e < TE; e++) acc[e] = 0.f;
#pragma unroll 2
    for (int k = 0; k < 100; k++) {
        const float wf = Wfc2[k * 192 + t];
        const float4* hr = reinterpret_cast<const float4*>(sh_h[k]);
        const float4 h0 = hr[0], h1 = hr[1], h2 = hr[2], h3 = hr[3];
        acc[0]  += h0.x * wf; acc[1]  += h0.y * wf;
        acc[2]  += h0.z * wf; acc[3]  += h0.w * wf;
        acc[4]  += h1.x * wf; acc[5]  += h1.y * wf;
        acc[6]  += h1.z * wf; acc[7]  += h1.w * wf;
        acc[8]  += h2.x * wf; acc[9]  += h2.y * wf;
        acc[10] += h2.z * wf; acc[11] += h2.w * wf;
        acc[12] += h3.x * wf; acc[13] += h3.y * wf;
        acc[14] += h3.z * wf; acc[15] += h3.w * wf;
    }
    const float SW = 0.025f;   // (1/sqrt(100)) * (1/sqrt(16))

    // Phase C: form messages + scatter
    if (t < 64) {
        const int j = t;
#pragma unroll 4
        for (int e = 0; e < TE; e++) {
            const int s = sh_src[e], d = sh_dst[e];
            const float y0 = g_l[s * NODE_F + j];
            atomicAdd(&g_s[d * S_F + j], acc[e] * SW * y0 * sh_ea[e][0]);
        }
    } else if (t < 128) {
        const int u = t - 64;
#pragma unroll 4
        for (int e = 0; e < TE; e++) {
            const int s = sh_src[e], d = sh_dst[e];
            const float y0 = g_l[s * NODE_F + u];
            const float base = acc[e] * SW * y0;
            float* p = &g_s[d * S_F + 64 + u * 3];
            atomicAdd(p + 0, base * sh_ea[e][1]);
            atomicAdd(p + 1, base * sh_ea[e][2]);
            atomicAdd(p + 2, base * sh_ea[e][3]);
        }
    } else if (t < 160) {
        const int u = t - 128;
#pragma unroll 4
        for (int e = 0; e < TE; e++) {
            const int s = sh_src[e], d = sh_dst[e];
            const float base = acc[e] * SW * sh_ea[e][0];
            const float* yl = &g_l[s * NODE_F + 64 + u * 3];
            float* p = &g_s[d * S_F + 256 + u * 3];
            atomicAdd(p + 0, base * yl[0]);
            atomicAdd(p + 1, base * yl[1]);
            atomicAdd(p + 2, base * yl[2]);
        }
    } else {
        const int u = t - 160;
#pragma unroll 4
        for (int e = 0; e < TE; e++) {
            const int s = sh_src[e], d = sh_dst[e];
            const float* yl = &g_l[s * NODE_F + 64 + u * 3];
            const float dotv = yl[0] * sh_ea[e][1] + yl[1] * sh_ea[e][2] +
                               yl[2] * sh_ea[e][3];
            atomicAdd(&g_s[d * S_F + 352 + u],
                      acc[e] * SW * dotv * 0.5773502691896258f);  // 1/sqrt(3)
        }
    }
}

// ---------------------------------------------------------------------------
// Node post-pass: out += 0.5 * (s @ W_l2) * a / sqrt(96). One block per node.
__global__ void node_post_kernel(const float* __restrict__ attr,
                                 const float* __restrict__ W00,
                                 const float* __restrict__ W10,
                                 const float* __restrict__ W01,
                                 const float* __restrict__ W11,
                                 float* __restrict__ out) {
    __shared__ float ss[S_F];
    const int n = blockIdx.x, t = threadIdx.x;
    for (int i = t; i < S_F; i += 160)
        ss[i] = g_s[n * S_F + i];
    __syncthreads();
    const float sc = attr[n] * 0.05103103630798287f;     // 0.5 / sqrt(96)
    float acc = 0.f;
    if (t < 64) {
#pragma unroll
        for (int u = 0; u < 64; u++) acc += ss[u] * W00[u * 64 + t];
#pragma unroll
        for (int u = 0; u < 32; u++) acc += ss[352 + u] * W10[u * 64 + t];
    } else {
        const int idx = t - 64;
        const int w = idx / 3, d = idx - w * 3;
#pragma unroll
        for (int u = 0; u < 64; u++) acc += ss[64 + u * 3 + d] * W01[u * 32 + w];
#pragma unroll
        for (int u = 0; u < 32; u++) acc += ss[256 + u * 3 + d] * W11[u * 32 + w];
    }
    out[n * NODE_F + t] += acc * sc;
}

// ---------------------------------------------------------------------------
extern "C" void kernel_launch(void* const* d_in, const int* in_sizes, int n_in,
                              void* d_out, int out_size) {
    const float* node_input = (const float*)d_in[0];
    const float* node_attr  = (const float*)d_in[1];
    const float* edge_attr  = (const float*)d_in[2];
    const float* elemb      = (const float*)d_in[3];
    const float* W_si0      = (const float*)d_in[4];
    const float* W_si1      = (const float*)d_in[5];
    const float* W_l1_0     = (const float*)d_in[6];
    const float* W_l1_1     = (const float*)d_in[7];
    const float* W_l2_00    = (const float*)d_in[8];
    const float* W_l2_10    = (const float*)d_in[9];
    const float* W_l2_01    = (const float*)d_in[10];
    const float* W_l2_11    = (const float*)d_in[11];
    const float* W_fc1      = (const float*)d_in[12];
    const float* W_fc2      = (const float*)d_in[13];
    const int*   esrc       = (const int*)d_in[14];
    const int*   edst       = (const int*)d_in[15];
    float* out = (float*)d_out;

    zero_s_kernel<<<1184, 256>>>();
    node_pre_kernel<<<N_NODES, 160>>>(node_input, node_attr,
                                      W_si0, W_si1, W_l1_0, W_l1_1, out);
    edge_kernel<<<N_EDGES / TE, 192>>>(elemb, edge_attr, esrc, edst,
                                       W_fc1, W_fc2);
    node_post_kernel<<<N_NODES, 160>>>(node_attr, W_l2_00, W_l2_10,
                                       W_l2_01, W_l2_11, out);
}